// round 1
// baseline (speedup 1.0000x reference)
#include <cuda_runtime.h>
#include <math.h>

// Problem constants
#define L_SEQ 2048
#define DIMC  1024
#define NST   16
#define BATCH 2
#define MROWS (BATCH * L_SEQ)     // 4096
#define XDW   (2 * NST + DIMC)    // 1056

// ---------------------------------------------------------------------------
// Device scratch (no allocation allowed -> __device__ globals)
// ---------------------------------------------------------------------------
__device__ float g_xz[(size_t)MROWS * 2048];            // GEMM1 out (x_c | z)
__device__ float g_xc[(size_t)MROWS * DIMC];            // conv+silu out, (b,l,d)
__device__ float g_xdbl[(size_t)MROWS * XDW];           // GEMM2 out
__device__ float g_zsT[(size_t)BATCH * DIMC * L_SEQ];   // silu(z), (b,d,l)
__device__ float g_dtxc[(size_t)BATCH * DIMC * L_SEQ * 2]; // (b,d,l,{dt,xc})
__device__ float g_bc[(size_t)BATCH * (L_SEQ / 2) * NST * 4]; // (b,l/2,n,{B0,C0,B1,C1})
__device__ float g_ybarT[(size_t)BATCH * DIMC * L_SEQ]; // scan out, (b,d,l)

// ---------------------------------------------------------------------------
// GEMM: C[m][n] = sum_k A[m][k] * B[n][k]
//   AT=false: A row-major (M,K)
//   AT=true : A is g_ybarT geometry: A'[k][m] at A[(m/2048)*2^21 + k*2048 + m%2048]
// B is row-major (N,K) weights. N-guarded (for N=1056).
// ---------------------------------------------------------------------------
template <bool AT>
__global__ __launch_bounds__(256, 2)
void gemm_kernel(const float* __restrict__ A, const float* __restrict__ B,
                 float* __restrict__ C, int M, int N, int K, int ldc)
{
    __shared__ float As[8][132];
    __shared__ float Bs[8][132];
    const int tid = threadIdx.x;
    const int bm = blockIdx.y << 7;
    const int bn = blockIdx.x << 7;

    const float* aptr;
    if (!AT) {
        aptr = A + (size_t)(bm + (tid >> 1)) * K + ((tid & 1) << 2);
    } else {
        int bb = bm >> 11;
        int l0 = bm & 2047;
        aptr = A + ((size_t)bb << 21) + ((size_t)(tid >> 5) << 11) + l0 + ((tid & 31) << 2);
    }
    const int brow = bn + (tid >> 1);
    const bool bval = brow < N;
    const float* bptr = B + (size_t)brow * K + ((tid & 1) << 2);

    const int trow = (tid >> 4) << 3;
    const int tcol = (tid & 15) << 3;

    float acc[8][8];
#pragma unroll
    for (int i = 0; i < 8; i++)
#pragma unroll
        for (int j = 0; j < 8; j++) acc[i][j] = 0.f;

    float4 aReg = *(const float4*)aptr;
    float4 bReg = bval ? *(const float4*)bptr : make_float4(0.f, 0.f, 0.f, 0.f);

    for (int k0 = 0; k0 < K; k0 += 8) {
        if (!AT) {
            int cc = (tid & 1) << 2, rr = tid >> 1;
            As[cc + 0][rr] = aReg.x; As[cc + 1][rr] = aReg.y;
            As[cc + 2][rr] = aReg.z; As[cc + 3][rr] = aReg.w;
        } else {
            *(float4*)&As[tid >> 5][(tid & 31) << 2] = aReg;
        }
        {
            int cc = (tid & 1) << 2, rr = tid >> 1;
            Bs[cc + 0][rr] = bReg.x; Bs[cc + 1][rr] = bReg.y;
            Bs[cc + 2][rr] = bReg.z; Bs[cc + 3][rr] = bReg.w;
        }
        __syncthreads();
        if (k0 + 8 < K) {
            aptr += AT ? (size_t)(8 << 11) : (size_t)8;
            bptr += 8;
            aReg = *(const float4*)aptr;
            bReg = bval ? *(const float4*)bptr : make_float4(0.f, 0.f, 0.f, 0.f);
        }
#pragma unroll
        for (int kk = 0; kk < 8; kk++) {
            float4 a0 = *(const float4*)&As[kk][trow];
            float4 a1 = *(const float4*)&As[kk][trow + 4];
            float4 b0 = *(const float4*)&Bs[kk][tcol];
            float4 b1 = *(const float4*)&Bs[kk][tcol + 4];
            float af[8] = {a0.x, a0.y, a0.z, a0.w, a1.x, a1.y, a1.z, a1.w};
            float bf[8] = {b0.x, b0.y, b0.z, b0.w, b1.x, b1.y, b1.z, b1.w};
#pragma unroll
            for (int i = 0; i < 8; i++)
#pragma unroll
                for (int j = 0; j < 8; j++)
                    acc[i][j] = fmaf(af[i], bf[j], acc[i][j]);
        }
        __syncthreads();
    }

#pragma unroll
    for (int i = 0; i < 8; i++) {
        float* crow = C + (size_t)(bm + trow + i) * ldc + bn + tcol;
        if (bn + tcol + 7 < N) {
            *(float4*)crow = make_float4(acc[i][0], acc[i][1], acc[i][2], acc[i][3]);
            *(float4*)(crow + 4) = make_float4(acc[i][4], acc[i][5], acc[i][6], acc[i][7]);
        } else {
#pragma unroll
            for (int j = 0; j < 8; j++)
                if (bn + tcol + j < N) crow[j] = acc[i][j];
        }
    }
}

// ---------------------------------------------------------------------------
// Depthwise causal conv(k=4) + bias + SiLU -> g_xc (natural layout)
// SiLU(z) -> g_zsT (transposed (b,d,l) layout for the scan)
// ---------------------------------------------------------------------------
__global__ void conv_kernel(const float* __restrict__ xz,
                            const float* __restrict__ cw,
                            const float* __restrict__ cb,
                            float* __restrict__ xc,
                            float* __restrict__ zsT)
{
    __shared__ float xs[35][33];
    __shared__ float zs[32][33];
    const int b = blockIdx.z;
    const int l0 = blockIdx.y << 5;
    const int d0 = blockIdx.x << 5;
    const int t = threadIdx.x;
    const int c = t & 31;
    const int r0 = t >> 5;

    for (int r = r0; r < 35; r += 8) {
        int l = l0 - 3 + r;
        xs[r][c] = (l >= 0) ? xz[((size_t)(b * L_SEQ + l) << 11) + d0 + c] : 0.f;
    }
    for (int r = r0; r < 32; r += 8) {
        float v = xz[((size_t)(b * L_SEQ + l0 + r) << 11) + DIMC + d0 + c];
        zs[r][c] = __fdividef(v, 1.f + __expf(-v));
    }
    __syncthreads();

    const float4 w = *(const float4*)(cw + (size_t)(d0 + c) * 4);
    const float bias = cb[d0 + c];
    for (int r = r0; r < 32; r += 8) {
        float v = w.x * xs[r][c] + w.y * xs[r + 1][c] + w.z * xs[r + 2][c]
                + w.w * xs[r + 3][c] + bias;
        v = __fdividef(v, 1.f + __expf(-v));
        xc[(size_t)(b * L_SEQ + l0 + r) * DIMC + d0 + c] = v;
    }
    __syncthreads();
    // transposed write of silu(z): r = local d, c = local l
    for (int r = r0; r < 32; r += 8) {
        zsT[(size_t)((b << 10) + d0 + r) * L_SEQ + l0 + c] = zs[c][r];
    }
}

// ---------------------------------------------------------------------------
// Build (b,d,l,{softplus(dt), xc}) interleaved stream for the scan
// ---------------------------------------------------------------------------
__global__ void dtxc_kernel(const float* __restrict__ xdbl,
                            const float* __restrict__ xc,
                            float* __restrict__ dtxc)
{
    __shared__ float sdt[32][33];
    __shared__ float sxc[32][33];
    const int b = blockIdx.z;
    const int l0 = blockIdx.y << 5;
    const int d0 = blockIdx.x << 5;
    const int t = threadIdx.x;
    const int c = t & 31;
    const int r0 = t >> 5;

    for (int r = r0; r < 32; r += 8) {
        float v = xdbl[(size_t)(b * L_SEQ + l0 + r) * XDW + 2 * NST + d0 + c];
        sdt[r][c] = (v > 15.f) ? v : log1pf(__expf(v));
        sxc[r][c] = xc[(size_t)(b * L_SEQ + l0 + r) * DIMC + d0 + c];
    }
    __syncthreads();
    for (int r = r0; r < 32; r += 8) {  // r: local d, c: local l
        float2 v = make_float2(sdt[c][r], sxc[c][r]);
        *(float2*)(dtxc + ((size_t)((b << 10) + d0 + r) * L_SEQ + l0 + c) * 2) = v;
    }
}

// ---------------------------------------------------------------------------
// Pack B_ssm/C_ssm as (b, l/2, n, {B(l),C(l),B(l+1),C(l+1)}) for float4 loads
// ---------------------------------------------------------------------------
__global__ void bc_kernel(const float* __restrict__ xdbl, float* __restrict__ bc)
{
    int idx = blockIdx.x * blockDim.x + threadIdx.x;
    if (idx >= BATCH * (L_SEQ / 2) * NST) return;
    int n = idx & 15;
    int l2 = (idx >> 4) & (L_SEQ / 2 - 1);
    int b = idx >> 14;
    const float* p = xdbl + (size_t)(b * L_SEQ + 2 * l2) * XDW;
    float4 v = make_float4(p[n], p[NST + n], p[XDW + n], p[XDW + NST + n]);
    *(float4*)(bc + (size_t)idx * 4) = v;
}

// ---------------------------------------------------------------------------
// Selective scan: 1 warp per 2 (b,d) channels; lane = (half, n).
// h_{l} = h_{l-1} * exp(-(n+1)*dt) + dt*B*xc ; y = sum_n h*C + D*xc ; *= silu(z)
// Software pipelined (1 iter ahead), 4 timesteps per iteration.
// ---------------------------------------------------------------------------
__global__ void scan_kernel(const float* __restrict__ dtxc,
                            const float* __restrict__ bc,
                            const float* __restrict__ zsT,
                            const float* __restrict__ Dp,
                            float* __restrict__ ybarT)
{
    const int warp = (blockIdx.x * blockDim.x + threadIdx.x) >> 5;
    const int lane = threadIdx.x & 31;
    const int b = warp >> 9;
    const int d = ((warp & 511) << 1) + (lane >> 4);
    const int n = lane & 15;
    const float An = -(float)(n + 1);
    const bool root = (n == 0);

    const size_t rowoff = (size_t)((b << 10) + d) * L_SEQ;
    const float* dxp = dtxc + rowoff * 2;
    const float* zp = zsT + rowoff;
    float* yp = ybarT + rowoff;
    const float* bcp = bc + ((size_t)b * (L_SEQ / 2) * NST + n) * 4;
    const float Dv = Dp[d];
    float h = 0.f;

    float4 v0 = *(const float4*)(dxp);
    float4 v1 = *(const float4*)(dxp + 4);
    float4 p01 = *(const float4*)(bcp);
    float4 p23 = *(const float4*)(bcp + 64);
    float4 zv = root ? *(const float4*)(zp) : make_float4(0.f, 0.f, 0.f, 0.f);

    for (int l = 0; l < L_SEQ; l += 4) {
        float4 cv0 = v0, cv1 = v1, cb01 = p01, cb23 = p23, cz = zv;
        const int ln = l + 4;
        if (ln < L_SEQ) {
            v0 = *(const float4*)(dxp + 2 * ln);
            v1 = *(const float4*)(dxp + 2 * ln + 4);
            const float* q = bcp + (size_t)(ln >> 1) * 64;
            p01 = *(const float4*)(q);
            p23 = *(const float4*)(q + 64);
            if (root) zv = *(const float4*)(zp + ln);
        }
        float4 yv;
        {   // step 0
            float dA = __expf(An * cv0.x);
            h = fmaf(h, dA, cv0.x * cv0.y * cb01.x);
            float pr = h * cb01.y;
            pr += __shfl_xor_sync(0xffffffffu, pr, 1);
            pr += __shfl_xor_sync(0xffffffffu, pr, 2);
            pr += __shfl_xor_sync(0xffffffffu, pr, 4);
            pr += __shfl_xor_sync(0xffffffffu, pr, 8);
            yv.x = fmaf(Dv, cv0.y, pr) * cz.x;
        }
        {   // step 1
            float dA = __expf(An * cv0.z);
            h = fmaf(h, dA, cv0.z * cv0.w * cb01.z);
            float pr = h * cb01.w;
            pr += __shfl_xor_sync(0xffffffffu, pr, 1);
            pr += __shfl_xor_sync(0xffffffffu, pr, 2);
            pr += __shfl_xor_sync(0xffffffffu, pr, 4);
            pr += __shfl_xor_sync(0xffffffffu, pr, 8);
            yv.y = fmaf(Dv, cv0.w, pr) * cz.y;
        }
        {   // step 2
            float dA = __expf(An * cv1.x);
            h = fmaf(h, dA, cv1.x * cv1.y * cb23.x);
            float pr = h * cb23.y;
            pr += __shfl_xor_sync(0xffffffffu, pr, 1);
            pr += __shfl_xor_sync(0xffffffffu, pr, 2);
            pr += __shfl_xor_sync(0xffffffffu, pr, 4);
            pr += __shfl_xor_sync(0xffffffffu, pr, 8);
            yv.z = fmaf(Dv, cv1.y, pr) * cz.z;
        }
        {   // step 3
            float dA = __expf(An * cv1.z);
            h = fmaf(h, dA, cv1.z * cv1.w * cb23.z);
            float pr = h * cb23.w;
            pr += __shfl_xor_sync(0xffffffffu, pr, 1);
            pr += __shfl_xor_sync(0xffffffffu, pr, 2);
            pr += __shfl_xor_sync(0xffffffffu, pr, 4);
            pr += __shfl_xor_sync(0xffffffffu, pr, 8);
            yv.w = fmaf(Dv, cv1.w, pr) * cz.w;
        }
        if (root) *(float4*)(yp + l) = yv;
    }
}

// ---------------------------------------------------------------------------
// kernel_launch
// ---------------------------------------------------------------------------
extern "C" void kernel_launch(void* const* d_in, const int* in_sizes, int n_in,
                              void* d_out, int out_size)
{
    (void)in_sizes; (void)n_in; (void)out_size;
    const float* x          = (const float*)d_in[0];
    const float* in_proj_w  = (const float*)d_in[1];
    const float* conv_w     = (const float*)d_in[2];
    const float* conv_b     = (const float*)d_in[3];
    const float* x_proj_w   = (const float*)d_in[4];
    const float* D_param    = (const float*)d_in[5];
    const float* out_proj_w = (const float*)d_in[6];
    float* out = (float*)d_out;

    float *xz, *xc, *xdbl, *zsT, *dtxc, *bcp, *ybarT;
    cudaGetSymbolAddress((void**)&xz, g_xz);
    cudaGetSymbolAddress((void**)&xc, g_xc);
    cudaGetSymbolAddress((void**)&xdbl, g_xdbl);
    cudaGetSymbolAddress((void**)&zsT, g_zsT);
    cudaGetSymbolAddress((void**)&dtxc, g_dtxc);
    cudaGetSymbolAddress((void**)&bcp, g_bc);
    cudaGetSymbolAddress((void**)&ybarT, g_ybarT);

    // 1) xz = x @ in_proj_w^T   (4096 x 2048)
    gemm_kernel<false><<<dim3(16, 32), 256>>>(x, in_proj_w, xz, MROWS, 2048, DIMC, 2048);

    // 2) depthwise conv + silu, silu(z) transpose
    conv_kernel<<<dim3(32, 64, 2), 256>>>(xz, conv_w, conv_b, xc, zsT);

    // 3) x_dbl = xc @ x_proj_w^T  (4096 x 1056)
    gemm_kernel<false><<<dim3(9, 32), 256>>>(xc, x_proj_w, xdbl, MROWS, XDW, DIMC, XDW);

    // 4) pack scan streams
    dtxc_kernel<<<dim3(32, 64, 2), 256>>>(xdbl, xc, dtxc);
    bc_kernel<<<64, 512>>>(xdbl, bcp);

    // 5) selective scan (+ D*xc, * silu(z)) -> ybarT (b,d,l)
    scan_kernel<<<128, 256>>>(dtxc, bcp, zsT, D_param, ybarT);

    // 6) out = ybar @ out_proj_w^T  (4096 x 1024), A read K-major from ybarT
    gemm_kernel<true><<<dim3(8, 32), 256>>>(ybarT, out_proj_w, out, MROWS, DIMC, DIMC, DIMC);
}

// round 4
// speedup vs baseline: 1.3106x; 1.3106x over previous
#include <cuda_runtime.h>
#include <math.h>
#include <stdint.h>

// Problem constants
#define L_SEQ 2048
#define DIMC  1024
#define NST   16
#define BATCH 2
#define MROWS (BATCH * L_SEQ)     // 4096
#define XDW   (2 * NST + DIMC)    // 1056
#define KDIM  1024
#define KTILES 32                 // KDIM / 32
#define PADK  36                  // smem floats per row (32 + 4 pad)

// ---------------------------------------------------------------------------
// Device scratch
// ---------------------------------------------------------------------------
__device__ float g_xz[(size_t)MROWS * 2048];
__device__ float g_xc[(size_t)MROWS * DIMC];
__device__ float g_xdbl[(size_t)MROWS * XDW];
__device__ float g_zsT[(size_t)BATCH * DIMC * L_SEQ];
__device__ float g_dtxc[(size_t)BATCH * DIMC * L_SEQ * 2];
__device__ float g_bc[(size_t)BATCH * (L_SEQ / 2) * NST * 4];
__device__ float g_y[(size_t)BATCH * L_SEQ * DIMC];     // scan out, natural (b,l,d)

// ---------------------------------------------------------------------------
// PTX helpers (arch-portable: cp.async + mma.sync, compute_80+)
// ---------------------------------------------------------------------------
__device__ __forceinline__ uint32_t smem_u32(const void* p) {
    uint32_t a;
    asm("{ .reg .u64 t; cvta.to.shared.u64 t, %1; cvt.u32.u64 %0, t; }" : "=r"(a) : "l"(p));
    return a;
}
__device__ __forceinline__ void cp_async16(uint32_t dst, const void* src, int src_bytes) {
    asm volatile("cp.async.cg.shared.global [%0], [%1], 16, %2;"
                 :: "r"(dst), "l"(src), "r"(src_bytes));
}
#define CP_COMMIT() asm volatile("cp.async.commit_group;" ::: "memory")
#define CP_WAIT(n)  asm volatile("cp.async.wait_group %0;" :: "n"(n) : "memory")

__device__ __forceinline__ void mma_tf32(float c[4], const uint32_t a[4], const uint32_t b[2]) {
    asm volatile(
        "mma.sync.aligned.m16n8k8.row.col.f32.tf32.tf32.f32 "
        "{%0,%1,%2,%3}, {%4,%5,%6,%7}, {%8,%9}, {%0,%1,%2,%3};"
        : "+f"(c[0]), "+f"(c[1]), "+f"(c[2]), "+f"(c[3])
        : "r"(a[0]), "r"(a[1]), "r"(a[2]), "r"(a[3]), "r"(b[0]), "r"(b[1]));
}
__device__ __forceinline__ float to_tf32(float x) {
    float y;
    asm("cvt.rna.tf32.f32 %0, %1;" : "=f"(y) : "f"(x));
    return y;
}

// ---------------------------------------------------------------------------
// Tensor-core GEMM (3xTF32 mma.sync, fp32-comparable accuracy):
// C[m][n] = sum_k A[m][k] * B[n][k], K=1024
// Block tile 128x128, 8 warps (2x4), warp tile 64x32, K-chunk 32,
// double-buffered smem via cp.async. Each operand split hi/lo; accumulate
// a_hi*b_hi + a_hi*b_lo + a_lo*b_hi.
// ---------------------------------------------------------------------------
__global__ __launch_bounds__(256, 2)
void gemm_mma(const float* __restrict__ A, const float* __restrict__ B,
              float* __restrict__ C, int N, int ldc)
{
    extern __shared__ float sm[];
    const uint32_t smem_base = smem_u32(sm);

    const int tid = threadIdx.x;
    const int wid = tid >> 5;
    const int lane = tid & 31;
    const int bm = (int)blockIdx.y << 7;
    const int bn = (int)blockIdx.x << 7;

    // cooperative-load mapping: row r (0..127), 2x float4 chunks in cols
    const int r = tid >> 1;
    const int ccol = (tid & 1) << 4;          // 0 or 16 (float col)
    const float* aptr = A + (size_t)(bm + r) * KDIM + ccol;
    const int brow = bn + r;
    const int bbytes = (brow < N) ? 16 : 0;   // zfill rows beyond N
    const float* bptr = B + (size_t)brow * KDIM + ccol;

    const uint32_t sA_st = smem_base + ((uint32_t)r * PADK + ccol) * 4u;
    const uint32_t sB_st = sA_st + 128u * PADK * 4u;
    const uint32_t STAGE = 2u * 128u * PADK * 4u;

    // warp tile coords
    const int wm = (wid & 1) << 6;            // 0 / 64
    const int wn = (wid >> 1) << 5;           // 0 / 32 / 64 / 96
    const int g = lane >> 2;                  // groupID
    const int tig = lane & 3;                 // threadID in group

    float acc[4][4][4];
#pragma unroll
    for (int mi = 0; mi < 4; mi++)
#pragma unroll
        for (int ni = 0; ni < 4; ni++)
#pragma unroll
            for (int q = 0; q < 4; q++) acc[mi][ni][q] = 0.f;

    // prologue: stage 0
#pragma unroll
    for (int j = 0; j < 4; j++) {
        cp_async16(sA_st + j * 16u, aptr + j * 4, 16);
        cp_async16(sB_st + j * 16u, bptr + j * 4, bbytes);
    }
    CP_COMMIT();

    const float* sAf = sm;

    for (int kt = 0; kt < KTILES; kt++) {
        const int st = kt & 1;
        if (kt + 1 < KTILES) {
            const uint32_t so = (uint32_t)((kt + 1) & 1) * STAGE;
            const float* ap = aptr + (kt + 1) * 32;
            const float* bp = bptr + (kt + 1) * 32;
#pragma unroll
            for (int j = 0; j < 4; j++) {
                cp_async16(sA_st + so + j * 16u, ap + j * 4, 16);
                cp_async16(sB_st + so + j * 16u, bp + j * 4, bbytes);
            }
            CP_COMMIT();
            CP_WAIT(1);
        } else {
            CP_WAIT(0);
        }
        __syncthreads();

        const float* As = sAf + (size_t)st * 2 * 128 * PADK;
        const float* Bs = As + 128 * PADK;
        const float* sa = As + (wm + g) * PADK + tig;
        const float* sb = Bs + (wn + g) * PADK + tig;

#pragma unroll
        for (int ks = 0; ks < 4; ks++) {
            // B fragments: hi/lo split
            uint32_t bh[4][2], bl[4][2];
#pragma unroll
            for (int ni = 0; ni < 4; ni++) {
                const float* p = sb + ni * 8 * PADK + ks * 8;
                float b0 = p[0], b1 = p[4];
                float h0 = to_tf32(b0), h1 = to_tf32(b1);
                bh[ni][0] = __float_as_uint(h0);
                bh[ni][1] = __float_as_uint(h1);
                bl[ni][0] = __float_as_uint(b0 - h0);
                bl[ni][1] = __float_as_uint(b1 - h1);
            }
#pragma unroll
            for (int mi = 0; mi < 4; mi++) {
                const float* p = sa + mi * 16 * PADK + ks * 8;
                float a0 = p[0], a1 = p[8 * PADK], a2 = p[4], a3 = p[8 * PADK + 4];
                float h0 = to_tf32(a0), h1 = to_tf32(a1);
                float h2 = to_tf32(a2), h3 = to_tf32(a3);
                uint32_t ah[4] = {__float_as_uint(h0), __float_as_uint(h1),
                                  __float_as_uint(h2), __float_as_uint(h3)};
                uint32_t al[4] = {__float_as_uint(a0 - h0), __float_as_uint(a1 - h1),
                                  __float_as_uint(a2 - h2), __float_as_uint(a3 - h3)};
#pragma unroll
                for (int ni = 0; ni < 4; ni++) {
                    mma_tf32(acc[mi][ni], al, bh[ni]);
                    mma_tf32(acc[mi][ni], ah, bl[ni]);
                    mma_tf32(acc[mi][ni], ah, bh[ni]);
                }
            }
        }
        __syncthreads();
    }

    // epilogue
#pragma unroll
    for (int mi = 0; mi < 4; mi++) {
        const int row = bm + wm + mi * 16 + g;
#pragma unroll
        for (int ni = 0; ni < 4; ni++) {
            const int col = bn + wn + ni * 8 + tig * 2;
            if (col < N) {
                *(float2*)(C + (size_t)row * ldc + col) =
                    make_float2(acc[mi][ni][0], acc[mi][ni][1]);
                *(float2*)(C + (size_t)(row + 8) * ldc + col) =
                    make_float2(acc[mi][ni][2], acc[mi][ni][3]);
            }
        }
    }
}

// ---------------------------------------------------------------------------
// Depthwise causal conv(k=4) + bias + SiLU -> g_xc; SiLU(z) -> g_zsT (b,d,l)
// ---------------------------------------------------------------------------
__global__ void conv_kernel(const float* __restrict__ xz,
                            const float* __restrict__ cw,
                            const float* __restrict__ cb,
                            float* __restrict__ xc,
                            float* __restrict__ zsT)
{
    __shared__ float xs[35][33];
    __shared__ float zs[32][33];
    const int b = blockIdx.z;
    const int l0 = blockIdx.y << 5;
    const int d0 = blockIdx.x << 5;
    const int t = threadIdx.x;
    const int c = t & 31;
    const int r0 = t >> 5;

    for (int r = r0; r < 35; r += 8) {
        int l = l0 - 3 + r;
        xs[r][c] = (l >= 0) ? xz[((size_t)(b * L_SEQ + l) << 11) + d0 + c] : 0.f;
    }
    for (int r = r0; r < 32; r += 8) {
        float v = xz[((size_t)(b * L_SEQ + l0 + r) << 11) + DIMC + d0 + c];
        zs[r][c] = __fdividef(v, 1.f + __expf(-v));
    }
    __syncthreads();

    const float4 w = *(const float4*)(cw + (size_t)(d0 + c) * 4);
    const float bias = cb[d0 + c];
    for (int r = r0; r < 32; r += 8) {
        float v = w.x * xs[r][c] + w.y * xs[r + 1][c] + w.z * xs[r + 2][c]
                + w.w * xs[r + 3][c] + bias;
        v = __fdividef(v, 1.f + __expf(-v));
        xc[(size_t)(b * L_SEQ + l0 + r) * DIMC + d0 + c] = v;
    }
    __syncthreads();
    for (int r = r0; r < 32; r += 8) {
        zsT[(size_t)((b << 10) + d0 + r) * L_SEQ + l0 + c] = zs[c][r];
    }
}

// ---------------------------------------------------------------------------
// Build (b,d,l,{softplus(dt), xc}) interleaved stream
// ---------------------------------------------------------------------------
__global__ void dtxc_kernel(const float* __restrict__ xdbl,
                            const float* __restrict__ xc,
                            float* __restrict__ dtxc)
{
    __shared__ float sdt[32][33];
    __shared__ float sxc[32][33];
    const int b = blockIdx.z;
    const int l0 = blockIdx.y << 5;
    const int d0 = blockIdx.x << 5;
    const int t = threadIdx.x;
    const int c = t & 31;
    const int r0 = t >> 5;

    for (int r = r0; r < 32; r += 8) {
        float v = xdbl[(size_t)(b * L_SEQ + l0 + r) * XDW + 2 * NST + d0 + c];
        sdt[r][c] = (v > 15.f) ? v : log1pf(__expf(v));
        sxc[r][c] = xc[(size_t)(b * L_SEQ + l0 + r) * DIMC + d0 + c];
    }
    __syncthreads();
    for (int r = r0; r < 32; r += 8) {
        float2 v = make_float2(sdt[c][r], sxc[c][r]);
        *(float2*)(dtxc + ((size_t)((b << 10) + d0 + r) * L_SEQ + l0 + c) * 2) = v;
    }
}

// ---------------------------------------------------------------------------
// Pack B_ssm/C_ssm as (b, l/2, n, {B0,C0,B1,C1})
// ---------------------------------------------------------------------------
__global__ void bc_kernel(const float* __restrict__ xdbl, float* __restrict__ bc)
{
    int idx = blockIdx.x * blockDim.x + threadIdx.x;
    if (idx >= BATCH * (L_SEQ / 2) * NST) return;
    int n = idx & 15;
    int l2 = (idx >> 4) & (L_SEQ / 2 - 1);
    int b = idx >> 14;
    const float* p = xdbl + (size_t)(b * L_SEQ + 2 * l2) * XDW;
    float4 v = make_float4(p[n], p[NST + n], p[XDW + n], p[XDW + NST + n]);
    *(float4*)(bc + (size_t)idx * 4) = v;
}

// ---------------------------------------------------------------------------
// Selective scan. Writes y in NATURAL (b,l,d) layout (float2 per l from lane0).
// ---------------------------------------------------------------------------
__global__ void scan_kernel(const float* __restrict__ dtxc,
                            const float* __restrict__ bc,
                            const float* __restrict__ zsT,
                            const float* __restrict__ Dp,
                            float* __restrict__ y)
{
    const int warp = (blockIdx.x * blockDim.x + threadIdx.x) >> 5;
    const int lane = threadIdx.x & 31;
    const int b = warp >> 9;
    const int d = ((warp & 511) << 1) + (lane >> 4);
    const int n = lane & 15;
    const float An = -(float)(n + 1);
    const bool root = (n == 0);

    const size_t rowoff = (size_t)((b << 10) + d) * L_SEQ;
    const float* dxp = dtxc + rowoff * 2;
    const float* zp = zsT + rowoff;
    const float* bcp = bc + ((size_t)b * (L_SEQ / 2) * NST + n) * 4;
    float* yb = y + ((size_t)b * L_SEQ) * DIMC + ((warp & 511) << 1);
    const float Dv = Dp[d];
    float h = 0.f;

    float4 v0 = *(const float4*)(dxp);
    float4 v1 = *(const float4*)(dxp + 4);
    float4 p01 = *(const float4*)(bcp);
    float4 p23 = *(const float4*)(bcp + 64);
    float4 zv = root ? *(const float4*)(zp) : make_float4(0.f, 0.f, 0.f, 0.f);

    for (int l = 0; l < L_SEQ; l += 4) {
        float4 cv0 = v0, cv1 = v1, cb01 = p01, cb23 = p23, cz = zv;
        const int ln = l + 4;
        if (ln < L_SEQ) {
            v0 = *(const float4*)(dxp + 2 * ln);
            v1 = *(const float4*)(dxp + 2 * ln + 4);
            const float* q = bcp + (size_t)(ln >> 1) * 64;
            p01 = *(const float4*)(q);
            p23 = *(const float4*)(q + 64);
            if (root) zv = *(const float4*)(zp + ln);
        }
        float4 yv;
        {
            float dA = __expf(An * cv0.x);
            h = fmaf(h, dA, cv0.x * cv0.y * cb01.x);
            float pr = h * cb01.y;
            pr += __shfl_xor_sync(0xffffffffu, pr, 1);
            pr += __shfl_xor_sync(0xffffffffu, pr, 2);
            pr += __shfl_xor_sync(0xffffffffu, pr, 4);
            pr += __shfl_xor_sync(0xffffffffu, pr, 8);
            yv.x = fmaf(Dv, cv0.y, pr) * cz.x;
        }
        {
            float dA = __expf(An * cv0.z);
            h = fmaf(h, dA, cv0.z * cv0.w * cb01.z);
            float pr = h * cb01.w;
            pr += __shfl_xor_sync(0xffffffffu, pr, 1);
            pr += __shfl_xor_sync(0xffffffffu, pr, 2);
            pr += __shfl_xor_sync(0xffffffffu, pr, 4);
            pr += __shfl_xor_sync(0xffffffffu, pr, 8);
            yv.y = fmaf(Dv, cv0.w, pr) * cz.y;
        }
        {
            float dA = __expf(An * cv1.x);
            h = fmaf(h, dA, cv1.x * cv1.y * cb23.x);
            float pr = h * cb23.y;
            pr += __shfl_xor_sync(0xffffffffu, pr, 1);
            pr += __shfl_xor_sync(0xffffffffu, pr, 2);
            pr += __shfl_xor_sync(0xffffffffu, pr, 4);
            pr += __shfl_xor_sync(0xffffffffu, pr, 8);
            yv.z = fmaf(Dv, cv1.y, pr) * cz.z;
        }
        {
            float dA = __expf(An * cv1.z);
            h = fmaf(h, dA, cv1.z * cv1.w * cb23.z);
            float pr = h * cb23.w;
            pr += __shfl_xor_sync(0xffffffffu, pr, 1);
            pr += __shfl_xor_sync(0xffffffffu, pr, 2);
            pr += __shfl_xor_sync(0xffffffffu, pr, 4);
            pr += __shfl_xor_sync(0xffffffffu, pr, 8);
            yv.w = fmaf(Dv, cv1.w, pr) * cz.w;
        }
        float u0 = __shfl_sync(0xffffffffu, yv.x, 16);
        float u1 = __shfl_sync(0xffffffffu, yv.y, 16);
        float u2 = __shfl_sync(0xffffffffu, yv.z, 16);
        float u3 = __shfl_sync(0xffffffffu, yv.w, 16);
        if (lane == 0) {
            *(float2*)(yb + (size_t)(l + 0) * DIMC) = make_float2(yv.x, u0);
            *(float2*)(yb + (size_t)(l + 1) * DIMC) = make_float2(yv.y, u1);
            *(float2*)(yb + (size_t)(l + 2) * DIMC) = make_float2(yv.z, u2);
            *(float2*)(yb + (size_t)(l + 3) * DIMC) = make_float2(yv.w, u3);
        }
    }
}

// ---------------------------------------------------------------------------
// kernel_launch
// ---------------------------------------------------------------------------
extern "C" void kernel_launch(void* const* d_in, const int* in_sizes, int n_in,
                              void* d_out, int out_size)
{
    (void)in_sizes; (void)n_in; (void)out_size;
    const float* x          = (const float*)d_in[0];
    const float* in_proj_w  = (const float*)d_in[1];
    const float* conv_w     = (const float*)d_in[2];
    const float* conv_b     = (const float*)d_in[3];
    const float* x_proj_w   = (const float*)d_in[4];
    const float* D_param    = (const float*)d_in[5];
    const float* out_proj_w = (const float*)d_in[6];
    float* out = (float*)d_out;

    float *xz, *xc, *xdbl, *zsT, *dtxc, *bcp, *ynat;
    cudaGetSymbolAddress((void**)&xz, g_xz);
    cudaGetSymbolAddress((void**)&xc, g_xc);
    cudaGetSymbolAddress((void**)&xdbl, g_xdbl);
    cudaGetSymbolAddress((void**)&zsT, g_zsT);
    cudaGetSymbolAddress((void**)&dtxc, g_dtxc);
    cudaGetSymbolAddress((void**)&bcp, g_bc);
    cudaGetSymbolAddress((void**)&ynat, g_y);

    const int SMEM_BYTES = 2 * 2 * 128 * PADK * 4;  // 73728
    cudaFuncSetAttribute(gemm_mma, cudaFuncAttributeMaxDynamicSharedMemorySize, SMEM_BYTES);

    // 1) xz = x @ in_proj_w^T   (4096 x 2048)
    gemm_mma<<<dim3(16, 32), 256, SMEM_BYTES>>>(x, in_proj_w, xz, 2048, 2048);

    // 2) depthwise conv + silu, silu(z) transpose
    conv_kernel<<<dim3(32, 64, 2), 256>>>(xz, conv_w, conv_b, xc, zsT);

    // 3) x_dbl = xc @ x_proj_w^T  (4096 x 1056)
    gemm_mma<<<dim3(9, 32), 256, SMEM_BYTES>>>(xc, x_proj_w, xdbl, 1056, 1056);

    // 4) pack scan streams
    dtxc_kernel<<<dim3(32, 64, 2), 256>>>(xdbl, xc, dtxc);
    bc_kernel<<<64, 512>>>(xdbl, bcp);

    // 5) selective scan -> y natural (b,l,d)
    scan_kernel<<<128, 256>>>(dtxc, bcp, zsT, D_param, ynat);

    // 6) out = y @ out_proj_w^T  (4096 x 1024)
    gemm_mma<<<dim3(8, 32), 256, SMEM_BYTES>>>(ynat, out_proj_w, out, 1024, 1024);
}

// round 5
// speedup vs baseline: 1.5731x; 1.2003x over previous
#include <cuda_runtime.h>
#include <cuda_fp16.h>
#include <math.h>
#include <stdint.h>

// Problem constants
#define L_SEQ 2048
#define DIMC  1024
#define NST   16
#define BATCH 2
#define MROWS (BATCH * L_SEQ)     // 4096
#define XDW   (2 * NST + DIMC)    // 1056
#define KDIM  1024
#define KTILES 32                 // KDIM / 32
#define PADH  40                  // smem halves per row (32 + 8 pad)
#define SEG   (128 * PADH)        // halves per operand buffer per stage

// ---------------------------------------------------------------------------
// Device scratch
// ---------------------------------------------------------------------------
__device__ float g_xz[(size_t)MROWS * 2048];
__device__ float g_xc[(size_t)MROWS * DIMC];
__device__ float g_xdbl[(size_t)MROWS * XDW];
__device__ float g_zsT[(size_t)BATCH * DIMC * L_SEQ];
__device__ float g_dtxc[(size_t)BATCH * DIMC * L_SEQ * 2];
__device__ float g_bc[(size_t)BATCH * (L_SEQ / 2) * NST * 4];

// fp16 hi/lo split operand buffers
__device__ __half g_xh[(size_t)MROWS * KDIM],   g_xl[(size_t)MROWS * KDIM];
__device__ __half g_wih[(size_t)2048 * KDIM],   g_wil[(size_t)2048 * KDIM];
__device__ __half g_wxh[(size_t)XDW * KDIM],    g_wxl[(size_t)XDW * KDIM];
__device__ __half g_woh[(size_t)DIMC * KDIM],   g_wol[(size_t)DIMC * KDIM];
__device__ __half g_xch[(size_t)MROWS * DIMC],  g_xcl[(size_t)MROWS * DIMC];
__device__ __half g_yh[(size_t)MROWS * DIMC],   g_yl[(size_t)MROWS * DIMC];

// ---------------------------------------------------------------------------
// PTX helpers
// ---------------------------------------------------------------------------
__device__ __forceinline__ uint32_t smem_u32(const void* p) {
    uint32_t a;
    asm("{ .reg .u64 t; cvta.to.shared.u64 t, %1; cvt.u32.u64 %0, t; }" : "=r"(a) : "l"(p));
    return a;
}
__device__ __forceinline__ void cp_async16(uint32_t dst, const void* src, int src_bytes) {
    asm volatile("cp.async.cg.shared.global [%0], [%1], 16, %2;"
                 :: "r"(dst), "l"(src), "r"(src_bytes));
}
#define CP_COMMIT() asm volatile("cp.async.commit_group;" ::: "memory")
#define CP_WAIT(n)  asm volatile("cp.async.wait_group %0;" :: "n"(n) : "memory")

__device__ __forceinline__ void mma_f16(float c[4], const uint32_t a[4], const uint32_t b[2]) {
    asm volatile(
        "mma.sync.aligned.m16n8k16.row.col.f32.f16.f16.f32 "
        "{%0,%1,%2,%3}, {%4,%5,%6,%7}, {%8,%9}, {%0,%1,%2,%3};"
        : "+f"(c[0]), "+f"(c[1]), "+f"(c[2]), "+f"(c[3])
        : "r"(a[0]), "r"(a[1]), "r"(a[2]), "r"(a[3]), "r"(b[0]), "r"(b[1]));
}

// ---------------------------------------------------------------------------
// fp32 -> (hi fp16, lo fp16) split, 4 elements per thread
// ---------------------------------------------------------------------------
__global__ void split_kernel(const float* __restrict__ src,
                             __half* __restrict__ hi, __half* __restrict__ lo, int n4)
{
    int i = blockIdx.x * blockDim.x + threadIdx.x;
    if (i >= n4) return;
    float4 v = ((const float4*)src)[i];
    __half h0 = __float2half_rn(v.x), h1 = __float2half_rn(v.y);
    __half h2 = __float2half_rn(v.z), h3 = __float2half_rn(v.w);
    ((half2*)hi)[2 * i]     = __halves2half2(h0, h1);
    ((half2*)hi)[2 * i + 1] = __halves2half2(h2, h3);
    ((half2*)lo)[2 * i] = __halves2half2(
        __float2half_rn(v.x - __half2float(h0)), __float2half_rn(v.y - __half2float(h1)));
    ((half2*)lo)[2 * i + 1] = __halves2half2(
        __float2half_rn(v.z - __half2float(h2)), __float2half_rn(v.w - __half2float(h3)));
}

// ---------------------------------------------------------------------------
// fp16-split GEMM: C[m][n] = sum_k A[m][k]*B[n][k], K=1024 (fp32-grade accuracy)
// Block 128x128, 8 warps (2x4), warp tile 64x32, K-chunk 32, double-buffered
// cp.async. 3 MMAs per k16: ah*bh + ah*bl + al*bh.
// ---------------------------------------------------------------------------
__global__ __launch_bounds__(256, 2)
void gemm_f16s(const __half* __restrict__ Ah, const __half* __restrict__ Al,
               const __half* __restrict__ Bh, const __half* __restrict__ Bl,
               float* __restrict__ C, int N, int ldc)
{
    extern __shared__ __half sh[];
    // per stage: [Ah | Al | Bh | Bl], each SEG halves
    const uint32_t smem_base = smem_u32(sh);
    const uint32_t STAGE_B = 4u * SEG * 2u;   // stage stride in bytes

    const int tid = threadIdx.x;
    const int wid = tid >> 5;
    const int lane = tid & 31;
    const int bm = (int)blockIdx.y << 7;
    const int bn = (int)blockIdx.x << 7;

    // cooperative load: row r (0..127), 16-half chunk hc (0 or 16)
    const int r = tid >> 1;
    const int hc = (tid & 1) << 4;
    const __half* Ahp = Ah + (size_t)(bm + r) * KDIM + hc;
    const __half* Alp = Al + (size_t)(bm + r) * KDIM + hc;
    const int brow = bn + r;
    const int bbytes = (brow < N) ? 16 : 0;
    const __half* Bhp = Bh + (size_t)brow * KDIM + hc;
    const __half* Blp = Bl + (size_t)brow * KDIM + hc;

    const uint32_t s_st = smem_base + ((uint32_t)r * PADH + hc) * 2u;

    // warp tile coords
    const int wm = (wid & 1) << 6;
    const int wn = (wid >> 1) << 5;
    const int g = lane >> 2;
    const int tig = lane & 3;

    float acc[4][4][4];
#pragma unroll
    for (int mi = 0; mi < 4; mi++)
#pragma unroll
        for (int ni = 0; ni < 4; ni++)
#pragma unroll
            for (int q = 0; q < 4; q++) acc[mi][ni][q] = 0.f;

    // prologue: stage 0
    cp_async16(s_st + 0u * SEG * 2u,       Ahp,     16);
    cp_async16(s_st + 0u * SEG * 2u + 16u, Ahp + 8, 16);
    cp_async16(s_st + 1u * SEG * 2u,       Alp,     16);
    cp_async16(s_st + 1u * SEG * 2u + 16u, Alp + 8, 16);
    cp_async16(s_st + 2u * SEG * 2u,       Bhp,     bbytes);
    cp_async16(s_st + 2u * SEG * 2u + 16u, Bhp + 8, bbytes);
    cp_async16(s_st + 3u * SEG * 2u,       Blp,     bbytes);
    cp_async16(s_st + 3u * SEG * 2u + 16u, Blp + 8, bbytes);
    CP_COMMIT();

    for (int kt = 0; kt < KTILES; kt++) {
        const int st = kt & 1;
        if (kt + 1 < KTILES) {
            const uint32_t so = (uint32_t)((kt + 1) & 1) * STAGE_B;
            const int ko = (kt + 1) * 32;
            cp_async16(s_st + so + 0u * SEG * 2u,       Ahp + ko,     16);
            cp_async16(s_st + so + 0u * SEG * 2u + 16u, Ahp + ko + 8, 16);
            cp_async16(s_st + so + 1u * SEG * 2u,       Alp + ko,     16);
            cp_async16(s_st + so + 1u * SEG * 2u + 16u, Alp + ko + 8, 16);
            cp_async16(s_st + so + 2u * SEG * 2u,       Bhp + ko,     bbytes);
            cp_async16(s_st + so + 2u * SEG * 2u + 16u, Bhp + ko + 8, bbytes);
            cp_async16(s_st + so + 3u * SEG * 2u,       Blp + ko,     bbytes);
            cp_async16(s_st + so + 3u * SEG * 2u + 16u, Blp + ko + 8, bbytes);
            CP_COMMIT();
            CP_WAIT(1);
        } else {
            CP_WAIT(0);
        }
        __syncthreads();

        const __half* As_h = sh + (size_t)st * 4 * SEG;
        const __half* As_l = As_h + SEG;
        const __half* Bs_h = As_h + 2 * SEG;
        const __half* Bs_l = As_h + 3 * SEG;

#pragma unroll
        for (int ks = 0; ks < 2; ks++) {
            const int kof = ks * 16 + 2 * tig;
            uint32_t bh[4][2], bl[4][2];
#pragma unroll
            for (int ni = 0; ni < 4; ni++) {
                const int bo = (wn + ni * 8 + g) * PADH + kof;
                bh[ni][0] = *(const uint32_t*)(Bs_h + bo);
                bh[ni][1] = *(const uint32_t*)(Bs_h + bo + 8);
                bl[ni][0] = *(const uint32_t*)(Bs_l + bo);
                bl[ni][1] = *(const uint32_t*)(Bs_l + bo + 8);
            }
#pragma unroll
            for (int mi = 0; mi < 4; mi++) {
                const int ao = (wm + mi * 16 + g) * PADH + kof;
                uint32_t ah[4], al[4];
                ah[0] = *(const uint32_t*)(As_h + ao);
                ah[1] = *(const uint32_t*)(As_h + ao + 8 * PADH);
                ah[2] = *(const uint32_t*)(As_h + ao + 8);
                ah[3] = *(const uint32_t*)(As_h + ao + 8 * PADH + 8);
                al[0] = *(const uint32_t*)(As_l + ao);
                al[1] = *(const uint32_t*)(As_l + ao + 8 * PADH);
                al[2] = *(const uint32_t*)(As_l + ao + 8);
                al[3] = *(const uint32_t*)(As_l + ao + 8 * PADH + 8);
#pragma unroll
                for (int ni = 0; ni < 4; ni++) {
                    mma_f16(acc[mi][ni], ah, bh[ni]);
                    mma_f16(acc[mi][ni], ah, bl[ni]);
                    mma_f16(acc[mi][ni], al, bh[ni]);
                }
            }
        }
        __syncthreads();
    }

    // epilogue
#pragma unroll
    for (int mi = 0; mi < 4; mi++) {
        const int row = bm + wm + mi * 16 + g;
#pragma unroll
        for (int ni = 0; ni < 4; ni++) {
            const int col = bn + wn + ni * 8 + tig * 2;
            if (col < N) {
                *(float2*)(C + (size_t)row * ldc + col) =
                    make_float2(acc[mi][ni][0], acc[mi][ni][1]);
                *(float2*)(C + (size_t)(row + 8) * ldc + col) =
                    make_float2(acc[mi][ni][2], acc[mi][ni][3]);
            }
        }
    }
}

// ---------------------------------------------------------------------------
// Depthwise causal conv(k=4) + bias + SiLU -> g_xc (+ hi/lo halves);
// SiLU(z) -> g_zsT (b,d,l)
// ---------------------------------------------------------------------------
__global__ void conv_kernel(const float* __restrict__ xz,
                            const float* __restrict__ cw,
                            const float* __restrict__ cb,
                            float* __restrict__ xc,
                            __half* __restrict__ xch,
                            __half* __restrict__ xcl,
                            float* __restrict__ zsT)
{
    __shared__ float xs[35][33];
    __shared__ float zs[32][33];
    const int b = blockIdx.z;
    const int l0 = blockIdx.y << 5;
    const int d0 = blockIdx.x << 5;
    const int t = threadIdx.x;
    const int c = t & 31;
    const int r0 = t >> 5;

    for (int r = r0; r < 35; r += 8) {
        int l = l0 - 3 + r;
        xs[r][c] = (l >= 0) ? xz[((size_t)(b * L_SEQ + l) << 11) + d0 + c] : 0.f;
    }
    for (int r = r0; r < 32; r += 8) {
        float v = xz[((size_t)(b * L_SEQ + l0 + r) << 11) + DIMC + d0 + c];
        zs[r][c] = __fdividef(v, 1.f + __expf(-v));
    }
    __syncthreads();

    const float4 w = *(const float4*)(cw + (size_t)(d0 + c) * 4);
    const float bias = cb[d0 + c];
    for (int r = r0; r < 32; r += 8) {
        float v = w.x * xs[r][c] + w.y * xs[r + 1][c] + w.z * xs[r + 2][c]
                + w.w * xs[r + 3][c] + bias;
        v = __fdividef(v, 1.f + __expf(-v));
        const size_t idx = (size_t)(b * L_SEQ + l0 + r) * DIMC + d0 + c;
        xc[idx] = v;
        __half hv = __float2half_rn(v);
        xch[idx] = hv;
        xcl[idx] = __float2half_rn(v - __half2float(hv));
    }
    __syncthreads();
    for (int r = r0; r < 32; r += 8) {
        zsT[(size_t)((b << 10) + d0 + r) * L_SEQ + l0 + c] = zs[c][r];
    }
}

// ---------------------------------------------------------------------------
// Build (b,d,l,{softplus(dt), xc}) interleaved stream
// ---------------------------------------------------------------------------
__global__ void dtxc_kernel(const float* __restrict__ xdbl,
                            const float* __restrict__ xc,
                            float* __restrict__ dtxc)
{
    __shared__ float sdt[32][33];
    __shared__ float sxc[32][33];
    const int b = blockIdx.z;
    const int l0 = blockIdx.y << 5;
    const int d0 = blockIdx.x << 5;
    const int t = threadIdx.x;
    const int c = t & 31;
    const int r0 = t >> 5;

    for (int r = r0; r < 32; r += 8) {
        float v = xdbl[(size_t)(b * L_SEQ + l0 + r) * XDW + 2 * NST + d0 + c];
        sdt[r][c] = (v > 15.f) ? v : log1pf(__expf(v));
        sxc[r][c] = xc[(size_t)(b * L_SEQ + l0 + r) * DIMC + d0 + c];
    }
    __syncthreads();
    for (int r = r0; r < 32; r += 8) {
        float2 v = make_float2(sdt[c][r], sxc[c][r]);
        *(float2*)(dtxc + ((size_t)((b << 10) + d0 + r) * L_SEQ + l0 + c) * 2) = v;
    }
}

// ---------------------------------------------------------------------------
// Pack B_ssm/C_ssm as (b, l/2, n, {B0,C0,B1,C1})
// ---------------------------------------------------------------------------
__global__ void bc_kernel(const float* __restrict__ xdbl, float* __restrict__ bc)
{
    int idx = blockIdx.x * blockDim.x + threadIdx.x;
    if (idx >= BATCH * (L_SEQ / 2) * NST) return;
    int n = idx & 15;
    int l2 = (idx >> 4) & (L_SEQ / 2 - 1);
    int b = idx >> 14;
    const float* p = xdbl + (size_t)(b * L_SEQ + 2 * l2) * XDW;
    float4 v = make_float4(p[n], p[NST + n], p[XDW + n], p[XDW + NST + n]);
    *(float4*)(bc + (size_t)idx * 4) = v;
}

// ---------------------------------------------------------------------------
// Selective scan. Emits y directly as hi/lo halves in natural (b,l,d) layout.
// ---------------------------------------------------------------------------
__global__ void scan_kernel(const float* __restrict__ dtxc,
                            const float* __restrict__ bc,
                            const float* __restrict__ zsT,
                            const float* __restrict__ Dp,
                            __half* __restrict__ yh,
                            __half* __restrict__ yl)
{
    const int warp = (blockIdx.x * blockDim.x + threadIdx.x) >> 5;
    const int lane = threadIdx.x & 31;
    const int b = warp >> 9;
    const int d = ((warp & 511) << 1) + (lane >> 4);
    const int n = lane & 15;
    const float An = -(float)(n + 1);
    const bool root = (n == 0);

    const size_t rowoff = (size_t)((b << 10) + d) * L_SEQ;
    const float* dxp = dtxc + rowoff * 2;
    const float* zp = zsT + rowoff;
    const float* bcp = bc + ((size_t)b * (L_SEQ / 2) * NST + n) * 4;
    const size_t ybase = ((size_t)b * L_SEQ) * DIMC + ((warp & 511) << 1);
    const float Dv = Dp[d];
    float h = 0.f;

    float4 v0 = *(const float4*)(dxp);
    float4 v1 = *(const float4*)(dxp + 4);
    float4 p01 = *(const float4*)(bcp);
    float4 p23 = *(const float4*)(bcp + 64);
    float4 zv = root ? *(const float4*)(zp) : make_float4(0.f, 0.f, 0.f, 0.f);

    for (int l = 0; l < L_SEQ; l += 4) {
        float4 cv0 = v0, cv1 = v1, cb01 = p01, cb23 = p23, cz = zv;
        const int ln = l + 4;
        if (ln < L_SEQ) {
            v0 = *(const float4*)(dxp + 2 * ln);
            v1 = *(const float4*)(dxp + 2 * ln + 4);
            const float* q = bcp + (size_t)(ln >> 1) * 64;
            p01 = *(const float4*)(q);
            p23 = *(const float4*)(q + 64);
            if (root) zv = *(const float4*)(zp + ln);
        }
        float4 yv;
        {
            float dA = __expf(An * cv0.x);
            h = fmaf(h, dA, cv0.x * cv0.y * cb01.x);
            float pr = h * cb01.y;
            pr += __shfl_xor_sync(0xffffffffu, pr, 1);
            pr += __shfl_xor_sync(0xffffffffu, pr, 2);
            pr += __shfl_xor_sync(0xffffffffu, pr, 4);
            pr += __shfl_xor_sync(0xffffffffu, pr, 8);
            yv.x = fmaf(Dv, cv0.y, pr) * cz.x;
        }
        {
            float dA = __expf(An * cv0.z);
            h = fmaf(h, dA, cv0.z * cv0.w * cb01.z);
            float pr = h * cb01.w;
            pr += __shfl_xor_sync(0xffffffffu, pr, 1);
            pr += __shfl_xor_sync(0xffffffffu, pr, 2);
            pr += __shfl_xor_sync(0xffffffffu, pr, 4);
            pr += __shfl_xor_sync(0xffffffffu, pr, 8);
            yv.y = fmaf(Dv, cv0.w, pr) * cz.y;
        }
        {
            float dA = __expf(An * cv1.x);
            h = fmaf(h, dA, cv1.x * cv1.y * cb23.x);
            float pr = h * cb23.y;
            pr += __shfl_xor_sync(0xffffffffu, pr, 1);
            pr += __shfl_xor_sync(0xffffffffu, pr, 2);
            pr += __shfl_xor_sync(0xffffffffu, pr, 4);
            pr += __shfl_xor_sync(0xffffffffu, pr, 8);
            yv.z = fmaf(Dv, cv1.y, pr) * cz.z;
        }
        {
            float dA = __expf(An * cv1.z);
            h = fmaf(h, dA, cv1.z * cv1.w * cb23.z);
            float pr = h * cb23.w;
            pr += __shfl_xor_sync(0xffffffffu, pr, 1);
            pr += __shfl_xor_sync(0xffffffffu, pr, 2);
            pr += __shfl_xor_sync(0xffffffffu, pr, 4);
            pr += __shfl_xor_sync(0xffffffffu, pr, 8);
            yv.w = fmaf(Dv, cv1.w, pr) * cz.w;
        }
        float u0 = __shfl_sync(0xffffffffu, yv.x, 16);
        float u1 = __shfl_sync(0xffffffffu, yv.y, 16);
        float u2 = __shfl_sync(0xffffffffu, yv.z, 16);
        float u3 = __shfl_sync(0xffffffffu, yv.w, 16);
        if (lane == 0) {
            float a[4] = {yv.x, yv.y, yv.z, yv.w};
            float bq[4] = {u0, u1, u2, u3};
#pragma unroll
            for (int q = 0; q < 4; q++) {
                __half ha = __float2half_rn(a[q]);
                __half hb = __float2half_rn(bq[q]);
                *(half2*)(yh + ybase + (size_t)(l + q) * DIMC) = __halves2half2(ha, hb);
                *(half2*)(yl + ybase + (size_t)(l + q) * DIMC) = __halves2half2(
                    __float2half_rn(a[q] - __half2float(ha)),
                    __float2half_rn(bq[q] - __half2float(hb)));
            }
        }
    }
}

// ---------------------------------------------------------------------------
// kernel_launch
// ---------------------------------------------------------------------------
extern "C" void kernel_launch(void* const* d_in, const int* in_sizes, int n_in,
                              void* d_out, int out_size)
{
    (void)in_sizes; (void)n_in; (void)out_size;
    const float* x          = (const float*)d_in[0];
    const float* in_proj_w  = (const float*)d_in[1];
    const float* conv_w     = (const float*)d_in[2];
    const float* conv_b     = (const float*)d_in[3];
    const float* x_proj_w   = (const float*)d_in[4];
    const float* D_param    = (const float*)d_in[5];
    const float* out_proj_w = (const float*)d_in[6];
    float* out = (float*)d_out;

    float *xz, *xc, *xdbl, *zsT, *dtxc, *bcp;
    __half *xh, *xl, *wih, *wil, *wxh, *wxl, *woh, *wol, *xch, *xcl, *yh, *yl;
    cudaGetSymbolAddress((void**)&xz, g_xz);
    cudaGetSymbolAddress((void**)&xc, g_xc);
    cudaGetSymbolAddress((void**)&xdbl, g_xdbl);
    cudaGetSymbolAddress((void**)&zsT, g_zsT);
    cudaGetSymbolAddress((void**)&dtxc, g_dtxc);
    cudaGetSymbolAddress((void**)&bcp, g_bc);
    cudaGetSymbolAddress((void**)&xh, g_xh);   cudaGetSymbolAddress((void**)&xl, g_xl);
    cudaGetSymbolAddress((void**)&wih, g_wih); cudaGetSymbolAddress((void**)&wil, g_wil);
    cudaGetSymbolAddress((void**)&wxh, g_wxh); cudaGetSymbolAddress((void**)&wxl, g_wxl);
    cudaGetSymbolAddress((void**)&woh, g_woh); cudaGetSymbolAddress((void**)&wol, g_wol);
    cudaGetSymbolAddress((void**)&xch, g_xch); cudaGetSymbolAddress((void**)&xcl, g_xcl);
    cudaGetSymbolAddress((void**)&yh, g_yh);   cudaGetSymbolAddress((void**)&yl, g_yl);

    const int SMEM_BYTES = 2 * 4 * SEG * 2;  // 2 stages x 4 operands x SEG halves
    cudaFuncSetAttribute(gemm_f16s, cudaFuncAttributeMaxDynamicSharedMemorySize, SMEM_BYTES);

    // 0) split inputs to fp16 hi/lo
    split_kernel<<<(MROWS * KDIM / 4 + 255) / 256, 256>>>(x, xh, xl, MROWS * KDIM / 4);
    split_kernel<<<(2048 * KDIM / 4 + 255) / 256, 256>>>(in_proj_w, wih, wil, 2048 * KDIM / 4);
    split_kernel<<<(XDW * KDIM / 4 + 255) / 256, 256>>>(x_proj_w, wxh, wxl, XDW * KDIM / 4);
    split_kernel<<<(DIMC * KDIM / 4 + 255) / 256, 256>>>(out_proj_w, woh, wol, DIMC * KDIM / 4);

    // 1) xz = x @ in_proj_w^T   (4096 x 2048)
    gemm_f16s<<<dim3(16, 32), 256, SMEM_BYTES>>>(xh, xl, wih, wil, xz, 2048, 2048);

    // 2) depthwise conv + silu (+ hi/lo emit), silu(z) transpose
    conv_kernel<<<dim3(32, 64, 2), 256>>>(xz, conv_w, conv_b, xc, xch, xcl, zsT);

    // 3) x_dbl = xc @ x_proj_w^T  (4096 x 1056)
    gemm_f16s<<<dim3(9, 32), 256, SMEM_BYTES>>>(xch, xcl, wxh, wxl, xdbl, 1056, 1056);

    // 4) pack scan streams
    dtxc_kernel<<<dim3(32, 64, 2), 256>>>(xdbl, xc, dtxc);
    bc_kernel<<<64, 512>>>(xdbl, bcp);

    // 5) selective scan -> y hi/lo halves, natural (b,l,d)
    scan_kernel<<<128, 256>>>(dtxc, bcp, zsT, D_param, yh, yl);

    // 6) out = y @ out_proj_w^T  (4096 x 1024)
    gemm_f16s<<<dim3(8, 32), 256, SMEM_BYTES>>>(yh, yl, woh, wol, out, 1024, 1024);
}